// round 1
// baseline (speedup 1.0000x reference)
#include <cuda_runtime.h>
#include <math.h>

// PQLayer forward:
//   ips[b,m,k] = dot(x[b, m*8:(m+1)*8], C[m,k,:])          (D=8)
//   codes      = one_hot(argmax_k ips)    (forward value of straight-through)
//   x_hat[b, m*8:(m+1)*8] = C[m, argmax, :]
//
// Shapes: B=16384, FEAT=512, M=64, K=256, D=8.
// Output buffer: x_hat (B*512 floats) followed by codes (B*M*K floats).

#define Bn   16384
#define FEAT 512
#define Mn   64
#define Kn   256
#define Dn   8
#define RPW  32      // rows (b values) handled per warp
#define WARPS 8      // warps per block

__global__ __launch_bounds__(WARPS * 32)
void pq_forward_kernel(const float* __restrict__ x,
                       const float* __restrict__ C,
                       float* __restrict__ xhat,
                       float* __restrict__ codes)
{
    const int m    = blockIdx.x;
    const int warp = threadIdx.x >> 5;
    const int lane = threadIdx.x & 31;

    // Each lane owns codewords k = lane*8 .. lane*8+7, register-resident.
    // C[m, k, :] is 8 contiguous floats; lane reads 256B contiguous -> warp
    // reads the full 8KB C[m] tile coalesced.
    float4 c[8][2];
    const float4* Cm = reinterpret_cast<const float4*>(
        C + ((size_t)m * Kn + (size_t)lane * 8) * Dn);
#pragma unroll
    for (int j = 0; j < 8; j++) {
        c[j][0] = __ldg(Cm + j * 2);
        c[j][1] = __ldg(Cm + j * 2 + 1);
    }

    const int b0 = (blockIdx.y * WARPS + warp) * RPW;

    for (int r = 0; r < RPW; r++) {
        const int b = b0 + r;

        // Broadcast-load the 8-float x sub-vector (same address all lanes).
        const float4* xp = reinterpret_cast<const float4*>(
            x + (size_t)b * FEAT + m * Dn);
        const float4 xa = __ldg(xp);
        const float4 xb = __ldg(xp + 1);

        // Local argmax over this lane's 8 codewords (strict > keeps first
        // occurrence, matching jnp.argmax tie-breaking within the lane).
        float best = -INFINITY;
        int   bidx = lane * 8;
#pragma unroll
        for (int j = 0; j < 8; j++) {
            float ip = xa.x * c[j][0].x + xa.y * c[j][0].y
                     + xa.z * c[j][0].z + xa.w * c[j][0].w
                     + xb.x * c[j][1].x + xb.y * c[j][1].y
                     + xb.z * c[j][1].z + xb.w * c[j][1].w;
            if (ip > best) { best = ip; bidx = lane * 8 + j; }
        }

        // Warp argmax; on ties prefer the lower index (first occurrence).
#pragma unroll
        for (int off = 16; off; off >>= 1) {
            float ov = __shfl_xor_sync(0xffffffffu, best, off);
            int   oi = __shfl_xor_sync(0xffffffffu, bidx, off);
            if (ov > best || (ov == best && oi < bidx)) { best = ov; bidx = oi; }
        }
        const int kmax = bidx;

        // Write the one-hot codes row: each lane writes its 8 floats (32B),
        // warp covers 1KB contiguous -> fully coalesced.
        float4 z0 = make_float4(0.f, 0.f, 0.f, 0.f);
        float4 z1 = z0;
        const bool owner = ((kmax >> 3) == lane);
        if (owner) {
            const int j = kmax & 7;
            if (j < 4) (&z0.x)[j] = 1.0f; else (&z1.x)[j - 4] = 1.0f;
        }
        float4* cp = reinterpret_cast<float4*>(
            codes + ((size_t)b * Mn + m) * Kn + (size_t)lane * 8);
        cp[0] = z0;
        cp[1] = z1;

        // x_hat: the lane owning kmax has C[m,kmax,:] in registers.
        if (owner) {
            const int j = kmax & 7;
            float4* xo = reinterpret_cast<float4*>(
                xhat + (size_t)b * FEAT + m * Dn);
            xo[0] = c[j][0];
            xo[1] = c[j][1];
        }
    }
}

extern "C" void kernel_launch(void* const* d_in, const int* in_sizes, int n_in,
                              void* d_out, int out_size)
{
    // metadata order: x (B*FEAT), C (M*K*D). Be defensive about ordering.
    const float* x = (const float*)d_in[0];
    const float* C = (const float*)d_in[1];
    if (in_sizes[0] == Mn * Kn * Dn && in_sizes[1] == Bn * FEAT) {
        x = (const float*)d_in[1];
        C = (const float*)d_in[0];
    }

    float* xhat  = (float*)d_out;
    float* codes = (float*)d_out + (size_t)Bn * FEAT;

    dim3 grid(Mn, Bn / (WARPS * RPW));  // (64, 64)
    dim3 block(WARPS * 32);             // 256 threads
    pq_forward_kernel<<<grid, block>>>(x, C, xhat, codes);
}

// round 2
// speedup vs baseline: 1.1067x; 1.1067x over previous
#include <cuda_runtime.h>
#include <math.h>

// PQLayer forward, split into two kernels:
//   K1 (compute-bound): argmax_k <x[b,m*8:], C[m,k,:]>  -> g_idx (u8 per (b,m))
//   K2 (store-bound):   codes = one_hot(g_idx), xhat = C[m, g_idx, :]
//
// Forward value of straight-through codes is exactly one_hot(argmax):
//   (hard - soft) + soft == hard elementwise in IEEE fp32 (0-s+s==0, 1-s+s==1).
//
// Shapes: B=16384, FEAT=512, M=64, K=256, D=8.
// Output buffer: x_hat (B*512 f32) followed by codes (B*M*K f32).

#define Bn    16384
#define FEAT  512
#define Mn    64
#define Kn    256
#define Dn    8

#define WARPS1 8
#define RPW1   32     // rows per warp in argmax kernel

#define WARPS2 8
#define RPW2   4      // rows per warp in writer kernel

__device__ unsigned char g_idx[(size_t)Bn * Mn];   // 1 MB scratch

typedef unsigned long long u64;

__device__ __forceinline__ u64 pack2(float lo, float hi) {
    u64 r; asm("mov.b64 %0, {%1,%2};" : "=l"(r) : "f"(lo), "f"(hi)); return r;
}
__device__ __forceinline__ void unpack2(u64 v, float& lo, float& hi) {
    asm("mov.b64 {%0,%1}, %2;" : "=f"(lo), "=f"(hi) : "l"(v));
}
__device__ __forceinline__ u64 fma2(u64 a, u64 b, u64 c) {
    u64 d; asm("fma.rn.f32x2 %0, %1, %2, %3;" : "=l"(d) : "l"(a), "l"(b), "l"(c)); return d;
}
__device__ __forceinline__ u64 mul2(u64 a, u64 b) {
    u64 d; asm("mul.rn.f32x2 %0, %1, %2;" : "=l"(d) : "l"(a), "l"(b)); return d;
}

// ---------------------------------------------------------------------------
// Kernel 1: argmax. Warp per (m, b-group); lane owns codewords lane*8..+7,
// packed two-codewords-per-f32x2 so each 64-bit FMA advances two dots.
// ---------------------------------------------------------------------------
__global__ __launch_bounds__(WARPS1 * 32)
void pq_argmax_kernel(const float* __restrict__ x, const float* __restrict__ C)
{
    const int m    = blockIdx.x;
    const int warp = threadIdx.x >> 5;
    const int lane = threadIdx.x & 31;

    // cc[p][d] = ( C[m, k0+2p, d] , C[m, k0+2p+1, d] ) with k0 = lane*8.
    u64 cc[4][8];
    const float4* Cm = reinterpret_cast<const float4*>(
        C + ((size_t)m * Kn + (size_t)lane * 8) * Dn);
#pragma unroll
    for (int p = 0; p < 4; p++) {
        float4 a0 = __ldg(Cm + 4 * p + 0);   // codeword 2p,   d 0..3
        float4 a1 = __ldg(Cm + 4 * p + 1);   // codeword 2p,   d 4..7
        float4 b0 = __ldg(Cm + 4 * p + 2);   // codeword 2p+1, d 0..3
        float4 b1 = __ldg(Cm + 4 * p + 3);   // codeword 2p+1, d 4..7
        cc[p][0] = pack2(a0.x, b0.x); cc[p][1] = pack2(a0.y, b0.y);
        cc[p][2] = pack2(a0.z, b0.z); cc[p][3] = pack2(a0.w, b0.w);
        cc[p][4] = pack2(a1.x, b1.x); cc[p][5] = pack2(a1.y, b1.y);
        cc[p][6] = pack2(a1.z, b1.z); cc[p][7] = pack2(a1.w, b1.w);
    }

    const int b0 = (blockIdx.y * WARPS1 + warp) * RPW1;

#pragma unroll 2
    for (int r = 0; r < RPW1; r++) {
        const int b = b0 + r;
        const float4* xp = reinterpret_cast<const float4*>(
            x + (size_t)b * FEAT + m * Dn);
        const float4 xa = __ldg(xp);
        const float4 xb = __ldg(xp + 1);
        u64 xx[8] = { pack2(xa.x, xa.x), pack2(xa.y, xa.y),
                      pack2(xa.z, xa.z), pack2(xa.w, xa.w),
                      pack2(xb.x, xb.x), pack2(xb.y, xb.y),
                      pack2(xb.z, xb.z), pack2(xb.w, xb.w) };

        float best = -INFINITY;
        int   bidx = 0;
#pragma unroll
        for (int p = 0; p < 4; p++) {
            u64 acc = mul2(cc[p][0], xx[0]);
#pragma unroll
            for (int d = 1; d < 8; d++) acc = fma2(cc[p][d], xx[d], acc);
            float f0, f1; unpack2(acc, f0, f1);
            const int k0 = lane * 8 + 2 * p;
            // strict > keeps lowest index on ties within the lane
            if (f0 > best) { best = f0; bidx = k0;     }
            if (f1 > best) { best = f1; bidx = k0 + 1; }
        }

        // Warp argmax via redux: max of order-preserving uint map, then
        // min index among lanes holding the max (first-occurrence).
        unsigned ord = __float_as_uint(best);
        ord = (ord & 0x80000000u) ? ~ord : (ord | 0x80000000u);
        const unsigned mx   = __reduce_max_sync(0xffffffffu, ord);
        const unsigned cand = (ord == mx) ? (unsigned)bidx : 0xFFFFFFFFu;
        const unsigned kmax = __reduce_min_sync(0xffffffffu, cand);

        if (lane == 0)
            g_idx[(size_t)b * Mn + m] = (unsigned char)kmax;
    }
}

// ---------------------------------------------------------------------------
// Kernel 2: streaming one-hot + xhat writer. Warp per 4 consecutive rows
// (row = b*Mn + m). Lane writes 32B of the 1KB codes row (fully coalesced);
// the owning lane also gathers C[m,k,:] (L2-resident) into xhat.
// ---------------------------------------------------------------------------
__global__ __launch_bounds__(WARPS2 * 32)
void pq_write_kernel(const float* __restrict__ C,
                     float* __restrict__ xhat,
                     float* __restrict__ codes)
{
    const int gwarp = blockIdx.x * WARPS2 + (threadIdx.x >> 5);
    const int lane  = threadIdx.x & 31;
    const int row0  = gwarp * RPW2;

    // 4 consecutive u8 indices in one aligned 32-bit load (broadcast).
    const unsigned packed =
        *reinterpret_cast<const unsigned*>(g_idx + row0);

#pragma unroll
    for (int r = 0; r < RPW2; r++) {
        const int  row   = row0 + r;
        const int  k     = (packed >> (8 * r)) & 0xFF;
        const bool owner = ((k >> 3) == lane);

        float4 z0 = make_float4(0.f, 0.f, 0.f, 0.f);
        float4 z1 = z0;
        if (owner) {
            const int j = k & 7;
            if (j < 4) (&z0.x)[j] = 1.0f; else (&z1.x)[j - 4] = 1.0f;
        }
        float4* cp = reinterpret_cast<float4*>(
            codes + (size_t)row * Kn + (size_t)lane * 8);
        cp[0] = z0;
        cp[1] = z1;

        if (owner) {
            const int m = row & (Mn - 1);
            const int b = row >> 6;
            const float4* cw = reinterpret_cast<const float4*>(
                C + ((size_t)m * Kn + k) * Dn);
            const float4 w0 = __ldg(cw);
            const float4 w1 = __ldg(cw + 1);
            float4* xo = reinterpret_cast<float4*>(
                xhat + (size_t)b * FEAT + m * Dn);
            xo[0] = w0;
            xo[1] = w1;
        }
    }
}

extern "C" void kernel_launch(void* const* d_in, const int* in_sizes, int n_in,
                              void* d_out, int out_size)
{
    // metadata order: x (B*FEAT), C (M*K*D). Be defensive about ordering.
    const float* x = (const float*)d_in[0];
    const float* C = (const float*)d_in[1];
    if (in_sizes[0] == Mn * Kn * Dn && in_sizes[1] == Bn * FEAT) {
        x = (const float*)d_in[1];
        C = (const float*)d_in[0];
    }

    float* xhat  = (float*)d_out;
    float* codes = (float*)d_out + (size_t)Bn * FEAT;

    {   // Kernel 1: argmax -> g_idx
        dim3 grid(Mn, Bn / (WARPS1 * RPW1));   // (64, 64)
        dim3 block(WARPS1 * 32);
        pq_argmax_kernel<<<grid, block>>>(x, C);
    }
    {   // Kernel 2: one-hot codes + xhat
        const int total_rows  = Bn * Mn;                    // 1,048,576
        const int total_warps = total_rows / RPW2;          // 262,144
        dim3 grid(total_warps / WARPS2);                    // 32,768
        dim3 block(WARPS2 * 32);
        pq_write_kernel<<<grid, block>>>(C, xhat, codes);
    }
}

// round 3
// speedup vs baseline: 2.1262x; 1.9212x over previous
#include <cuda_runtime.h>
#include <math.h>

// PQLayer forward, fully fused:
//   per (b,m): k* = argmax_k <x[b,m*8:+8], C[m,k,:]>
//   codes[b,m,:] = one_hot(k*)   (forward value of straight-through)
//   xhat[b,m*8:+8] = C[m,k*,:]
//
// Straight-through forward: (hard - soft) + soft == hard exactly in IEEE fp32.
//
// Shapes: B=16384, FEAT=512, M=64, K=256, D=8.
// d_out: xhat (B*512 f32) then codes (B*M*K f32).
//
// Design: block = (one m, 256 rows). x tile staged through smem with
// coalesced full-MLP loads; lane owns 8 codewords register-resident, packed
// 2-per-f32x2; warp argmax via redux; 1KB one-hot row emitted with one
// st.global.v8.b32 per lane. Compute hides under the 1.07GB store stream.

#define Bn    16384
#define FEAT  512
#define Mn    64
#define Kn    256
#define Dn    8
#define WARPS 8
#define RPW   32
#define TILEB (WARPS * RPW)   // 256 rows per block

typedef unsigned long long u64;
typedef unsigned int u32;

__device__ __forceinline__ u64 pack2(float lo, float hi) {
    u64 r; asm("mov.b64 %0, {%1,%2};" : "=l"(r) : "f"(lo), "f"(hi)); return r;
}
__device__ __forceinline__ void unpack2(u64 v, float& lo, float& hi) {
    asm("mov.b64 {%0,%1}, %2;" : "=f"(lo), "=f"(hi) : "l"(v));
}
__device__ __forceinline__ u64 fma2(u64 a, u64 b, u64 c) {
    u64 d; asm("fma.rn.f32x2 %0, %1, %2, %3;" : "=l"(d) : "l"(a), "l"(b), "l"(c)); return d;
}
__device__ __forceinline__ u64 mul2(u64 a, u64 b) {
    u64 d; asm("mul.rn.f32x2 %0, %1, %2;" : "=l"(d) : "l"(a), "l"(b)); return d;
}
__device__ __forceinline__ void stg256(void* p, u32 r0, u32 r1, u32 r2, u32 r3,
                                       u32 r4, u32 r5, u32 r6, u32 r7) {
    asm volatile("st.global.v8.b32 [%0], {%1,%2,%3,%4,%5,%6,%7,%8};"
                 :: "l"(p), "r"(r0), "r"(r1), "r"(r2), "r"(r3),
                    "r"(r4), "r"(r5), "r"(r6), "r"(r7) : "memory");
}

__global__ __launch_bounds__(TILEB)
void pq_fused_kernel(const float* __restrict__ x,
                     const float* __restrict__ C,
                     float* __restrict__ xhat,
                     float* __restrict__ codes)
{
    __shared__ float xs[TILEB * Dn];   // 8 KB: x sub-vectors for this tile

    const int m    = blockIdx.x;
    const int warp = threadIdx.x >> 5;
    const int lane = threadIdx.x & 31;
    const int tid  = threadIdx.x;
    const int btile = blockIdx.y * TILEB;

    // ---- Stage x tile: 256 rows x 32B, coalesced float4 loads (2 per thread,
    // each warp-instr touches 16 distinct 2KB-strided lines -> MLP=16).
#pragma unroll
    for (int pass = 0; pass < 2; pass++) {
        const int f    = pass * TILEB + tid;     // float4 id, 0..511
        const int row  = f >> 1;
        const int half = f & 1;
        reinterpret_cast<float4*>(xs)[f] = __ldg(reinterpret_cast<const float4*>(
            x + (size_t)(btile + row) * FEAT + m * Dn + half * 4));
    }

    // ---- Codebook: lane owns k = lane*8..+7, packed two codewords per f32x2.
    // cc[p][d] = ( C[m,k0+2p,d], C[m,k0+2p+1,d] ),  k0 = lane*8.
    u64 cc[4][8];
    {
        const float4* Cm = reinterpret_cast<const float4*>(
            C + ((size_t)m * Kn + (size_t)lane * 8) * Dn);
#pragma unroll
        for (int p = 0; p < 4; p++) {
            float4 a0 = __ldg(Cm + 4 * p + 0);
            float4 a1 = __ldg(Cm + 4 * p + 1);
            float4 b0 = __ldg(Cm + 4 * p + 2);
            float4 b1 = __ldg(Cm + 4 * p + 3);
            cc[p][0] = pack2(a0.x, b0.x); cc[p][1] = pack2(a0.y, b0.y);
            cc[p][2] = pack2(a0.z, b0.z); cc[p][3] = pack2(a0.w, b0.w);
            cc[p][4] = pack2(a1.x, b1.x); cc[p][5] = pack2(a1.y, b1.y);
            cc[p][6] = pack2(a1.z, b1.z); cc[p][7] = pack2(a1.w, b1.w);
        }
    }
    __syncthreads();

    const float* xw = xs + warp * RPW * Dn;

    for (int r = 0; r < RPW; r++) {
        // Broadcast LDS of this row's 8 floats (conflict-free).
        const float4 xa = reinterpret_cast<const float4*>(xw + r * Dn)[0];
        const float4 xb = reinterpret_cast<const float4*>(xw + r * Dn)[1];
        u64 xx[8] = { pack2(xa.x, xa.x), pack2(xa.y, xa.y),
                      pack2(xa.z, xa.z), pack2(xa.w, xa.w),
                      pack2(xb.x, xb.x), pack2(xb.y, xb.y),
                      pack2(xb.z, xb.z), pack2(xb.w, xb.w) };

        // 4 independent 8-deep FMA2 chains: 8 dot products per lane.
        float best = -INFINITY;
        int   bidx = 0;
#pragma unroll
        for (int p = 0; p < 4; p++) {
            u64 acc = mul2(cc[p][0], xx[0]);
#pragma unroll
            for (int d = 1; d < 8; d++) acc = fma2(cc[p][d], xx[d], acc);
            float f0, f1; unpack2(acc, f0, f1);
            const int k0 = lane * 8 + 2 * p;
            if (f0 > best) { best = f0; bidx = k0;     }   // strict >: first-occ
            if (f1 > best) { best = f1; bidx = k0 + 1; }
        }

        // Warp argmax: redux max on order-preserving uint, then min index
        // among tied lanes (lane order == k order -> first occurrence).
        u32 ord = __float_as_uint(best);
        ord = (ord & 0x80000000u) ? ~ord : (ord | 0x80000000u);
        const u32 mx   = __reduce_max_sync(0xffffffffu, ord);
        const u32 cand = (ord == mx) ? (u32)bidx : 0xFFFFFFFFu;
        const int kmax = (int)__reduce_min_sync(0xffffffffu, cand);

        const int  b     = btile + warp * RPW + r;
        const bool owner = ((kmax >> 3) == lane);
        const int  j     = kmax & 7;

        // One-hot row: lane emits its 32B in a single 256-bit store.
        u32 v[8];
#pragma unroll
        for (int i = 0; i < 8; i++)
            v[i] = (owner && j == i) ? 0x3f800000u : 0u;
        stg256(codes + ((size_t)b * Mn + m) * Kn + (size_t)lane * 8,
               v[0], v[1], v[2], v[3], v[4], v[5], v[6], v[7]);

        // xhat: owner re-fetches C[m,kmax,:] (L2-resident 2MB) and stores 32B.
        if (owner) {
            const float4* cw = reinterpret_cast<const float4*>(
                C + ((size_t)m * Kn + kmax) * Dn);
            const float4 w0 = __ldg(cw);
            const float4 w1 = __ldg(cw + 1);
            stg256(xhat + (size_t)b * FEAT + m * Dn,
                   __float_as_uint(w0.x), __float_as_uint(w0.y),
                   __float_as_uint(w0.z), __float_as_uint(w0.w),
                   __float_as_uint(w1.x), __float_as_uint(w1.y),
                   __float_as_uint(w1.z), __float_as_uint(w1.w));
        }
    }
}

extern "C" void kernel_launch(void* const* d_in, const int* in_sizes, int n_in,
                              void* d_out, int out_size)
{
    // metadata order: x (B*FEAT), C (M*K*D). Defensive about ordering.
    const float* x = (const float*)d_in[0];
    const float* C = (const float*)d_in[1];
    if (in_sizes[0] == Mn * Kn * Dn && in_sizes[1] == Bn * FEAT) {
        x = (const float*)d_in[1];
        C = (const float*)d_in[0];
    }

    float* xhat  = (float*)d_out;
    float* codes = (float*)d_out + (size_t)Bn * FEAT;

    dim3 grid(Mn, Bn / TILEB);    // (64, 64)
    dim3 block(TILEB);            // 256 threads
    pq_fused_kernel<<<grid, block>>>(x, C, xhat, codes);
}

// round 4
// speedup vs baseline: 2.4389x; 1.1471x over previous
#include <cuda_runtime.h>
#include <math.h>

// PQLayer forward, fully fused (R4):
//   per (b,m): k* = argmax_k <x[b,m*8:+8], C[m,k,:]>
//   codes[b,m,:] = one_hot(k*)   (exact forward value of straight-through)
//   xhat[b,m*8:+8] = C[m,k*,:]
//
// R4 changes vs R3: constant-zero v8 one-hot stores + scalar 1.0 patch by the
// owner lane (kills per-row SEL generation), and row-pair pipelining so the
// two serial redux chains of adjacent rows overlap.
// Dot-product summation order is kept IDENTICAL to R3 (sequential d, k-pair
// packed f32x2) -> bit-identical argmax vs the passing kernel.

#define Bn    16384
#define FEAT  512
#define Mn    64
#define Kn    256
#define Dn    8
#define WARPS 8
#define RPW   32
#define TILEB (WARPS * RPW)   // 256 rows per block

typedef unsigned long long u64;
typedef unsigned int u32;

__device__ __forceinline__ u64 pack2(float lo, float hi) {
    u64 r; asm("mov.b64 %0, {%1,%2};" : "=l"(r) : "f"(lo), "f"(hi)); return r;
}
__device__ __forceinline__ void unpack2(u64 v, float& lo, float& hi) {
    asm("mov.b64 {%0,%1}, %2;" : "=f"(lo), "=f"(hi) : "l"(v));
}
__device__ __forceinline__ u64 fma2(u64 a, u64 b, u64 c) {
    u64 d; asm("fma.rn.f32x2 %0, %1, %2, %3;" : "=l"(d) : "l"(a), "l"(b), "l"(c)); return d;
}
__device__ __forceinline__ u64 mul2(u64 a, u64 b) {
    u64 d; asm("mul.rn.f32x2 %0, %1, %2;" : "=l"(d) : "l"(a), "l"(b)); return d;
}
__device__ __forceinline__ void stg256_zero(void* p, u32 z) {
    asm volatile("st.global.v8.b32 [%0], {%1,%1,%1,%1,%1,%1,%1,%1};"
                 :: "l"(p), "r"(z) : "memory");
}
__device__ __forceinline__ void stg256(void* p, u32 r0, u32 r1, u32 r2, u32 r3,
                                       u32 r4, u32 r5, u32 r6, u32 r7) {
    asm volatile("st.global.v8.b32 [%0], {%1,%2,%3,%4,%5,%6,%7,%8};"
                 :: "l"(p), "r"(r0), "r"(r1), "r"(r2), "r"(r3),
                    "r"(r4), "r"(r5), "r"(r6), "r"(r7) : "memory");
}

// Per-row dot+local-argmax, order identical to R3.
__device__ __forceinline__ void row_dots(const float* __restrict__ xrow,
                                         const u64 cc[4][8], int lane,
                                         float& best, int& bidx)
{
    const float4 xa = reinterpret_cast<const float4*>(xrow)[0];
    const float4 xb = reinterpret_cast<const float4*>(xrow)[1];
    u64 xx[8] = { pack2(xa.x, xa.x), pack2(xa.y, xa.y),
                  pack2(xa.z, xa.z), pack2(xa.w, xa.w),
                  pack2(xb.x, xb.x), pack2(xb.y, xb.y),
                  pack2(xb.z, xb.z), pack2(xb.w, xb.w) };
    best = -INFINITY;
    bidx = 0;
#pragma unroll
    for (int p = 0; p < 4; p++) {
        u64 acc = mul2(cc[p][0], xx[0]);
#pragma unroll
        for (int d = 1; d < 8; d++) acc = fma2(cc[p][d], xx[d], acc);
        float f0, f1; unpack2(acc, f0, f1);
        const int k0 = lane * 8 + 2 * p;
        if (f0 > best) { best = f0; bidx = k0;     }   // strict >: first-occ
        if (f1 > best) { best = f1; bidx = k0 + 1; }
    }
}

__device__ __forceinline__ int warp_argmax(float best, int bidx)
{
    u32 ord = __float_as_uint(best);
    ord = (ord & 0x80000000u) ? ~ord : (ord | 0x80000000u);
    const u32 mx   = __reduce_max_sync(0xffffffffu, ord);
    const u32 cand = (ord == mx) ? (u32)bidx : 0xFFFFFFFFu;
    return (int)__reduce_min_sync(0xffffffffu, cand);
}

__global__ __launch_bounds__(TILEB, 2)
void pq_fused_kernel(const float* __restrict__ x,
                     const float* __restrict__ C,
                     float* __restrict__ xhat,
                     float* __restrict__ codes)
{
    __shared__ float xs[TILEB * Dn];   // 8 KB x tile

    const int m     = blockIdx.x;
    const int warp  = threadIdx.x >> 5;
    const int lane  = threadIdx.x & 31;
    const int tid   = threadIdx.x;
    const int btile = blockIdx.y * TILEB;

    // ---- Stage x tile (coalesced, MLP=16 per warp-instr).
#pragma unroll
    for (int pass = 0; pass < 2; pass++) {
        const int f    = pass * TILEB + tid;
        const int row  = f >> 1;
        const int half = f & 1;
        reinterpret_cast<float4*>(xs)[f] = __ldg(reinterpret_cast<const float4*>(
            x + (size_t)(btile + row) * FEAT + m * Dn + half * 4));
    }

    // ---- Codebook cache: lane owns k = lane*8..+7, two codewords per f32x2.
    u64 cc[4][8];
    {
        const float4* Cm = reinterpret_cast<const float4*>(
            C + ((size_t)m * Kn + (size_t)lane * 8) * Dn);
#pragma unroll
        for (int p = 0; p < 4; p++) {
            float4 a0 = __ldg(Cm + 4 * p + 0);
            float4 a1 = __ldg(Cm + 4 * p + 1);
            float4 b0 = __ldg(Cm + 4 * p + 2);
            float4 b1 = __ldg(Cm + 4 * p + 3);
            cc[p][0] = pack2(a0.x, b0.x); cc[p][1] = pack2(a0.y, b0.y);
            cc[p][2] = pack2(a0.z, b0.z); cc[p][3] = pack2(a0.w, b0.w);
            cc[p][4] = pack2(a1.x, b1.x); cc[p][5] = pack2(a1.y, b1.y);
            cc[p][6] = pack2(a1.z, b1.z); cc[p][7] = pack2(a1.w, b1.w);
        }
    }
    __syncthreads();

    const float* xw = xs + warp * RPW * Dn;
    const int    brow0 = btile + warp * RPW;
    // Lane's slice of the codes row; advances by one row (Mn*Kn floats) per b.
    float* crow = codes + ((size_t)brow0 * Mn + m) * Kn + (size_t)lane * 8;
    const u32 z = 0u;

    for (int r = 0; r < RPW; r += 2) {
        // --- dots for the row pair (independent chains, compiler interleaves)
        float bestA, bestB; int idxA, idxB;
        row_dots(xw + (r + 0) * Dn, cc, lane, bestA, idxA);
        row_dots(xw + (r + 1) * Dn, cc, lane, bestB, idxB);

        // --- the two redux chains overlap their latency
        const int kA = warp_argmax(bestA, idxA);
        const int kB = warp_argmax(bestB, idxB);

        // --- stores, row A
        {
            const int b = brow0 + r;
            float* cp = crow;
            stg256_zero(cp, z);
            if ((kA >> 3) == lane) {
                // patch the 1.0 (same thread as the zero store -> ordered)
                *(cp + (kA & 7)) = 1.0f;
                const float4* cw = reinterpret_cast<const float4*>(
                    C + ((size_t)m * Kn + kA) * Dn);
                const float4 w0 = __ldg(cw);
                const float4 w1 = __ldg(cw + 1);
                stg256(xhat + (size_t)b * FEAT + m * Dn,
                       __float_as_uint(w0.x), __float_as_uint(w0.y),
                       __float_as_uint(w0.z), __float_as_uint(w0.w),
                       __float_as_uint(w1.x), __float_as_uint(w1.y),
                       __float_as_uint(w1.z), __float_as_uint(w1.w));
            }
        }
        // --- stores, row B
        {
            const int b = brow0 + r + 1;
            float* cp = crow + (size_t)Mn * Kn;
            stg256_zero(cp, z);
            if ((kB >> 3) == lane) {
                *(cp + (kB & 7)) = 1.0f;
                const float4* cw = reinterpret_cast<const float4*>(
                    C + ((size_t)m * Kn + kB) * Dn);
                const float4 w0 = __ldg(cw);
                const float4 w1 = __ldg(cw + 1);
                stg256(xhat + (size_t)b * FEAT + m * Dn,
                       __float_as_uint(w0.x), __float_as_uint(w0.y),
                       __float_as_uint(w0.z), __float_as_uint(w0.w),
                       __float_as_uint(w1.x), __float_as_uint(w1.y),
                       __float_as_uint(w1.z), __float_as_uint(w1.w));
            }
        }
        crow += (size_t)2 * Mn * Kn;
    }
}

extern "C" void kernel_launch(void* const* d_in, const int* in_sizes, int n_in,
                              void* d_out, int out_size)
{
    // metadata order: x (B*FEAT), C (M*K*D). Defensive about ordering.
    const float* x = (const float*)d_in[0];
    const float* C = (const float*)d_in[1];
    if (in_sizes[0] == Mn * Kn * Dn && in_sizes[1] == Bn * FEAT) {
        x = (const float*)d_in[1];
        C = (const float*)d_in[0];
    }

    float* xhat  = (float*)d_out;
    float* codes = (float*)d_out + (size_t)Bn * FEAT;

    dim3 grid(Mn, Bn / TILEB);    // (64, 64)
    dim3 block(TILEB);            // 256 threads
    pq_fused_kernel<<<grid, block>>>(x, C, xhat, codes);
}